// round 6
// baseline (speedup 1.0000x reference)
#include <cuda_runtime.h>
#include <math.h>

// Problem constants (shapes fixed for this problem instance)
#define NN 100000
#define NE 1000000
#define NBLK 391          // ceil(NN/256)

// ---------------- scratch (static device globals; no allocation) ----------
__device__ float g_xl  [NN * 64];           // x @ W_l
__device__ float g_sout[NN];                // dot(out[n], W_att[0:64])
__device__ float g_wc  [32];                // W_e @ W_att[64:128]
__device__ float g_c0;                      // b_e . W_att[64:128] + b_att
__device__ float g_sums[128];               // [0:64) sum, [64:128) sumsq
__device__ float2 g_coef[64];               // fused BN*2 scale/shift
// CSR build
__device__ int   g_cnt2[NN];                // in-degree histogram
__device__ int   g_off [NN + 1];            // exclusive offsets
__device__ int   g_pos [NN];                // running fill cursor
__device__ int   g_bsum[512];               // per-block partial sums
__device__ int   g_boff[512];               // scanned partials
__device__ unsigned long long g_epack[NE];  // (eid<<32)|row, grouped by col

// ---------------- packed f32x2 helpers -------------------------------------
__device__ __forceinline__ unsigned long long pk2(float a, float b) {
    unsigned long long r;
    asm("mov.b64 %0, {%1, %2};" : "=l"(r) : "f"(a), "f"(b));
    return r;
}
__device__ __forceinline__ void ffma2(unsigned long long& d,
                                      unsigned long long a,
                                      unsigned long long b) {
    asm("fma.rn.f32x2 %0, %1, %2, %0;" : "+l"(d) : "l"(a), "l"(b));
}
__device__ __forceinline__ float lo32(unsigned long long v) {
    return __uint_as_float((unsigned)(v & 0xffffffffu));
}
__device__ __forceinline__ float hi32(unsigned long long v) {
    return __uint_as_float((unsigned)(v >> 32));
}

// ---------------- K0: zero scratch ----------------------------------------
__global__ void zero_kernel() {
    int i = blockIdx.x * blockDim.x + threadIdx.x;
    if (i < NN)  g_cnt2[i] = 0;
    if (i < 128) g_sums[i] = 0.0f;
}

// ---------------- Kp: prep wc = W_e @ a2, c0 = b_e.a2 + b_att --------------
__global__ void prep_kernel(const float* __restrict__ We,
                            const float* __restrict__ be,
                            const float* __restrict__ watt,
                            const float* __restrict__ batt) {
    int l = threadIdx.x;  // 32 threads
    float s = 0.f;
    #pragma unroll
    for (int j = 0; j < 64; j++) s = fmaf(We[l * 64 + j], watt[64 + j], s);
    g_wc[l] = s;
    float c = be[l] * watt[64 + l] + be[l + 32] * watt[64 + l + 32];
    #pragma unroll
    for (int o = 16; o > 0; o >>= 1) c += __shfl_xor_sync(0xffffffffu, c, o);
    if (l == 0) g_c0 = c + batt[0];
}

// ---------------- CSR build: histogram ------------------------------------
__global__ void hist_kernel(const int* __restrict__ ei, int E) {
    int e = blockIdx.x * blockDim.x + threadIdx.x;
    if (e >= E) return;
    atomicAdd(g_cnt2 + __ldg(ei + E + e), 1);
}

// ---------------- CSR build: 3-phase exclusive scan ------------------------
__global__ void scanA_kernel() {
    __shared__ int s[256];
    int t = threadIdx.x;
    int i = blockIdx.x * 256 + t;
    int v = (i < NN) ? g_cnt2[i] : 0;
    s[t] = v;
    __syncthreads();
    #pragma unroll
    for (int off = 1; off < 256; off <<= 1) {
        int add = (t >= off) ? s[t - off] : 0;
        __syncthreads();
        s[t] += add;
        __syncthreads();
    }
    if (t == 255) g_bsum[blockIdx.x] = s[255];
}

__global__ void scanB_kernel() {
    __shared__ int s[512];
    int t = threadIdx.x;
    int v = (t < NBLK) ? g_bsum[t] : 0;
    s[t] = v;
    __syncthreads();
    #pragma unroll
    for (int off = 1; off < 512; off <<= 1) {
        int add = (t >= off) ? s[t - off] : 0;
        __syncthreads();
        s[t] += add;
        __syncthreads();
    }
    if (t < NBLK) g_boff[t] = s[t] - v;   // exclusive
}

__global__ void scanC_kernel() {
    __shared__ int s[256];
    int t = threadIdx.x;
    int i = blockIdx.x * 256 + t;
    int v = (i < NN) ? g_cnt2[i] : 0;
    s[t] = v;
    __syncthreads();
    #pragma unroll
    for (int off = 1; off < 256; off <<= 1) {
        int add = (t >= off) ? s[t - off] : 0;
        __syncthreads();
        s[t] += add;
        __syncthreads();
    }
    int base = g_boff[blockIdx.x];
    if (i < NN) {
        int excl = base + s[t] - v;
        g_off[i] = excl;
        g_pos[i] = excl;
        if (i == NN - 1) g_off[NN] = excl + v;   // == E
    }
}

// ---------------- CSR build: fill (eid,row) packed records -----------------
__global__ void fill_kernel(const int* __restrict__ ei, int E) {
    int e = blockIdx.x * blockDim.x + threadIdx.x;
    if (e >= E) return;
    int r = __ldg(ei + e);
    int c = __ldg(ei + E + e);
    int p = atomicAdd(g_pos + c, 1);
    g_epack[p] = ((unsigned long long)(unsigned)e << 32) | (unsigned)r;
}

// ---------------- K1: fused node GEMM: xl = x@W_l, out = x@W_r (f32x2) -----
__global__ void node_gemm_kernel(const float* __restrict__ x,
                                 const float* __restrict__ Wl,
                                 const float* __restrict__ Wr,
                                 float* __restrict__ out, int N) {
    extern __shared__ float sm[];
    float* Wc = sm;                                   // 128x128 = 64KB
    const int tid  = threadIdx.x;
    const int lane = tid & 31;
    const int wid  = tid >> 5;
    float* xs = sm + 128 * 128 + wid * (8 * 128);     // 8 rows x 128 per warp

    for (int i = tid; i < 128 * 64; i += blockDim.x) {
        int k = i >> 6, j = i & 63;
        Wc[k * 128 + j]      = Wl[i];
        Wc[k * 128 + 64 + j] = Wr[i];
    }
    __syncthreads();

    int base = (blockIdx.x * 8 + wid) * 8;            // N % 8 == 0
    if (base >= N) return;

    const float4* xg = (const float4*)(x + (size_t)base * 128);
    #pragma unroll
    for (int i = 0; i < 8; i++)
        ((float4*)xs)[lane + 32 * i] = xg[lane + 32 * i];
    __syncwarp();

    unsigned long long acc[8][2];
    #pragma unroll
    for (int r = 0; r < 8; r++) { acc[r][0] = 0ull; acc[r][1] = 0ull; }

    #pragma unroll 4
    for (int k = 0; k < 128; k++) {
        ulonglong2 wv = *(const ulonglong2*)(Wc + k * 128 + lane * 4);
        #pragma unroll
        for (int r = 0; r < 8; r++) {
            unsigned long long xx = pk2(xs[r * 128 + k], xs[r * 128 + k]);
            ffma2(acc[r][0], xx, wv.x);
            ffma2(acc[r][1], xx, wv.y);
        }
    }

    #pragma unroll
    for (int r = 0; r < 8; r++) {
        int row = base + r;
        ulonglong2 v; v.x = acc[r][0]; v.y = acc[r][1];
        if (lane < 16)
            *(ulonglong2*)(g_xl + (size_t)row * 64 + lane * 4) = v;
        else
            *(ulonglong2*)(out + (size_t)row * 64 + (lane - 16) * 4) = v;
    }
}

// ---------------- K2: per-node gather-mean + finalize + s_out --------------
// Warp per node. 2 half-warps process 2 edges/iter; 16 lanes x float4 = row.
__global__ void gather_fin_kernel(const float* __restrict__ bl,
                                  const float* __restrict__ watt,
                                  float* __restrict__ out, int N) {
    int n = blockIdx.x * 8 + (threadIdx.x >> 5);
    if (n >= N) return;
    int lane = threadIdx.x & 31;
    int grp = lane >> 4, l = lane & 15;

    int beg = __ldg(g_off + n), end = __ldg(g_off + n + 1);
    float4 acc = make_float4(0.f, 0.f, 0.f, 0.f);
    for (int i = beg + grp; i < end; i += 2) {
        int r = (int)(unsigned)(__ldg(g_epack + i) & 0xffffffffull);
        float4 v = *(const float4*)(g_xl + (size_t)r * 64 + l * 4);
        acc.x += v.x; acc.y += v.y; acc.z += v.z; acc.w += v.w;
    }
    acc.x += __shfl_xor_sync(0xffffffffu, acc.x, 16);
    acc.y += __shfl_xor_sync(0xffffffffu, acc.y, 16);
    acc.z += __shfl_xor_sync(0xffffffffu, acc.z, 16);
    acc.w += __shfl_xor_sync(0xffffffffu, acc.w, 16);

    if (grp == 0) {
        float inv = 1.0f / fmaxf((float)(end - beg), 1.0f);
        float4 o = *(const float4*)(out + (size_t)n * 64 + l * 4);
        float4 b = ((const float4*)bl)[l];
        o.x = fmaf(acc.x, inv, o.x) + b.x;
        o.y = fmaf(acc.y, inv, o.y) + b.y;
        o.z = fmaf(acc.z, inv, o.z) + b.z;
        o.w = fmaf(acc.w, inv, o.w) + b.w;
        *(float4*)(out + (size_t)n * 64 + l * 4) = o;
        float4 w = ((const float4*)watt)[l];   // W_att[0:64]
        float p = o.x * w.x + o.y * w.y + o.z * w.z + o.w * w.w;
        p += __shfl_xor_sync(0x0000ffffu, p, 1);
        p += __shfl_xor_sync(0x0000ffffu, p, 2);
        p += __shfl_xor_sync(0x0000ffffu, p, 4);
        p += __shfl_xor_sync(0x0000ffffu, p, 8);
        if (l == 0) g_sout[n] = p;
    }
}

// ---------------- K3: per-node attention + epilogue + BN stats -------------
// Warp per node: 4 groups of 8 lanes, 4 edges/iter. Z, asum in registers —
// no atomics. In-loop reductions use the 8-lane GROUP mask (groups have
// different trip counts; a full-warp mask there deadlocks).
__global__ void __launch_bounds__(256)
attn_kernel(const float* __restrict__ ea,
            const float* __restrict__ We,
            const float* __restrict__ be,
            float* __restrict__ out, int N) {
    __shared__ float sWe[2048];
    __shared__ float sZ[8][32];
    __shared__ float ss[64], sq[64];

    int tid = threadIdx.x;
    int wid = tid >> 5, lane = tid & 31;
    #pragma unroll
    for (int i = 0; i < 2; i++)
        ((float4*)sWe)[tid + 256 * i] = ((const float4*)We)[tid + 256 * i];
    if (tid < 64) { ss[tid] = 0.f; sq[tid] = 0.f; }
    __syncthreads();

    int n = blockIdx.x * 8 + wid;
    float s0 = 0.f, q0 = 0.f, s1 = 0.f, q1 = 0.f;
    if (n < N) {
        int grp = lane >> 3, l = lane & 7;
        unsigned gmask = 0xFFu << (grp * 8);   // convergent 8-lane group
        int beg = __ldg(g_off + n), end = __ldg(g_off + n + 1);
        float zbias = g_sout[n] + g_c0;
        float4 wc4 = ((const float4*)g_wc)[l];

        float4 accZ = make_float4(0.f, 0.f, 0.f, 0.f);
        float asum = 0.f;
        for (int i = beg + grp; i < end; i += 4) {
            unsigned eid = (unsigned)(__ldg(g_epack + i) >> 32);
            float4 a = __ldg((const float4*)ea + (size_t)eid * 8 + l);
            float p = a.x * wc4.x + a.y * wc4.y + a.z * wc4.z + a.w * wc4.w;
            p += __shfl_xor_sync(gmask, p, 1);
            p += __shfl_xor_sync(gmask, p, 2);
            p += __shfl_xor_sync(gmask, p, 4);
            float att = 1.0f / (1.0f + __expf(-(p + zbias)));
            accZ.x = fmaf(att, a.x, accZ.x);
            accZ.y = fmaf(att, a.y, accZ.y);
            accZ.z = fmaf(att, a.z, accZ.z);
            accZ.w = fmaf(att, a.w, accZ.w);
            if (l == 0) asum += att;
        }
        // combine the 4 groups (all 32 lanes reconverge here; full mask OK)
        #pragma unroll
        for (int o = 8; o <= 16; o <<= 1) {
            accZ.x += __shfl_xor_sync(0xffffffffu, accZ.x, o);
            accZ.y += __shfl_xor_sync(0xffffffffu, accZ.y, o);
            accZ.z += __shfl_xor_sync(0xffffffffu, accZ.z, o);
            accZ.w += __shfl_xor_sync(0xffffffffu, accZ.w, o);
        }
        #pragma unroll
        for (int o = 1; o <= 16; o <<= 1)
            asum += __shfl_xor_sync(0xffffffffu, asum, o);
        if (lane < 8) ((float4*)sZ[wid])[lane] = accZ;
        __syncwarp();

        unsigned long long acc =
            *(const unsigned long long*)(out + (size_t)n * 64 + 2 * lane);
        unsigned long long be2 =
            *(const unsigned long long*)(be + 2 * lane);
        ffma2(acc, pk2(asum, asum), be2);
        #pragma unroll
        for (int k = 0; k < 32; k++) {
            float zk = sZ[wid][k];
            unsigned long long w2 =
                *(const unsigned long long*)(sWe + k * 64 + 2 * lane);
            ffma2(acc, pk2(zk, zk), w2);
        }
        *(unsigned long long*)(out + (size_t)n * 64 + 2 * lane) = acc;
        float v0 = lo32(acc), v1 = hi32(acc);
        s0 = v0; q0 = v0 * v0; s1 = v1; q1 = v1 * v1;
    }
    __syncthreads();
    atomicAdd(&ss[2 * lane],     s0);
    atomicAdd(&ss[2 * lane + 1], s1);
    atomicAdd(&sq[2 * lane],     q0);
    atomicAdd(&sq[2 * lane + 1], q1);
    __syncthreads();
    if (tid < 64) {
        atomicAdd(g_sums + tid,      ss[tid]);
        atomicAdd(g_sums + 64 + tid, sq[tid]);
    }
}

// ---------------- K5b: fold BN + residual-double into scale/shift ----------
__global__ void bn_coef_kernel(const float* __restrict__ gamma,
                               const float* __restrict__ beta, float invN) {
    int c = threadIdx.x;
    float mu  = g_sums[c] * invN;
    float var = g_sums[64 + c] * invN - mu * mu;
    float r = rsqrtf(var + 1e-5f);
    float g = gamma[c];
    g_coef[c] = make_float2(2.0f * g * r, 2.0f * (beta[c] - g * mu * r));
}

// ---------------- K6: apply -------------------------------------------------
__global__ void bn_apply_kernel(float* __restrict__ out, int total) {
    int i = blockIdx.x * blockDim.x + threadIdx.x;
    if (i >= total) return;
    float2 cs = g_coef[i & 63];
    out[i] = fmaxf(fmaf(out[i], cs.x, cs.y), 0.0f);
}

// ---------------- launch ----------------------------------------------------
extern "C" void kernel_launch(void* const* d_in, const int* in_sizes, int n_in,
                              void* d_out, int out_size) {
    const float* x     = (const float*)d_in[0];
    const int*   ei    = (const int*)  d_in[1];
    const float* ea    = (const float*)d_in[2];
    const float* Wl    = (const float*)d_in[3];
    const float* bl    = (const float*)d_in[4];
    const float* Wr    = (const float*)d_in[5];
    const float* We    = (const float*)d_in[6];
    const float* be    = (const float*)d_in[7];
    const float* watt  = (const float*)d_in[8];
    const float* batt  = (const float*)d_in[9];
    const float* gamma = (const float*)d_in[10];
    const float* beta  = (const float*)d_in[11];
    float* out = (float*)d_out;

    int N = in_sizes[0] / 128;   // 100000
    int E = in_sizes[1] / 2;     // 1000000

    cudaFuncSetAttribute(node_gemm_kernel,
                         cudaFuncAttributeMaxDynamicSharedMemorySize, 98304);

    zero_kernel<<<NBLK, 256>>>();
    prep_kernel<<<1, 32>>>(We, be, watt, batt);
    hist_kernel<<<(E + 255) / 256, 256>>>(ei, E);
    scanA_kernel<<<NBLK, 256>>>();
    scanB_kernel<<<1, 512>>>();
    scanC_kernel<<<NBLK, 256>>>();
    fill_kernel<<<(E + 255) / 256, 256>>>(ei, E);
    node_gemm_kernel<<<(N + 63) / 64, 256, 98304>>>(x, Wl, Wr, out, N);
    gather_fin_kernel<<<(N + 7) / 8, 256>>>(bl, watt, out, N);
    attn_kernel<<<(N + 7) / 8, 256>>>(ea, We, be, out, N);
    bn_coef_kernel<<<1, 64>>>(gamma, beta, 1.0f / (float)N);
    bn_apply_kernel<<<(N * 64 + 255) / 256, 256>>>(out, N * 64);
}

// round 8
// speedup vs baseline: 1.1523x; 1.1523x over previous
#include <cuda_runtime.h>
#include <math.h>

// Problem constants (shapes fixed for this problem instance)
#define NN 100000
#define NE 1000000
#define NBLK 391          // ceil(NN/256)
#define FGRID 1184        // fused kernel grid (8*148)
#define FCHUNK 85         // ceil(NN/FGRID)

// ---------------- scratch (static device globals; no allocation) ----------
__device__ float g_xl  [NN * 64];           // x @ W_l
__device__ float g_wc  [32];                // W_e @ W_att[64:128]
__device__ float g_c0;                      // b_e . W_att[64:128] + b_att
__device__ float g_sums[128];               // [0:64) sum, [64:128) sumsq
__device__ float2 g_coef[64];               // fused BN*2 scale/shift
// CSR build
__device__ int   g_cnt2[NN];                // in-degree histogram
__device__ int   g_off [NN + 1];            // exclusive offsets
__device__ int   g_pos [NN];                // running fill cursor
__device__ int   g_bsum[512];               // per-block partial sums
__device__ int   g_boff[512];               // scanned partials
__device__ unsigned long long g_epack[NE];  // (eid<<32)|row, grouped by col

// ---------------- packed f32x2 helpers -------------------------------------
__device__ __forceinline__ unsigned long long pk2(float a, float b) {
    unsigned long long r;
    asm("mov.b64 %0, {%1, %2};" : "=l"(r) : "f"(a), "f"(b));
    return r;
}
__device__ __forceinline__ void ffma2(unsigned long long& d,
                                      unsigned long long a,
                                      unsigned long long b) {
    asm("fma.rn.f32x2 %0, %1, %2, %0;" : "+l"(d) : "l"(a), "l"(b));
}
__device__ __forceinline__ float lo32(unsigned long long v) {
    return __uint_as_float((unsigned)(v & 0xffffffffu));
}
__device__ __forceinline__ float hi32(unsigned long long v) {
    return __uint_as_float((unsigned)(v >> 32));
}

// ---------------- K0: zero scratch ----------------------------------------
__global__ void zero_kernel() {
    int i = blockIdx.x * blockDim.x + threadIdx.x;
    if (i < NN)  g_cnt2[i] = 0;
    if (i < 128) g_sums[i] = 0.0f;
}

// ---------------- Kp: prep wc = W_e @ a2, c0 = b_e.a2 + b_att --------------
__global__ void prep_kernel(const float* __restrict__ We,
                            const float* __restrict__ be,
                            const float* __restrict__ watt,
                            const float* __restrict__ batt) {
    int l = threadIdx.x;  // 32 threads
    float s = 0.f;
    #pragma unroll
    for (int j = 0; j < 64; j++) s = fmaf(We[l * 64 + j], watt[64 + j], s);
    g_wc[l] = s;
    float c = be[l] * watt[64 + l] + be[l + 32] * watt[64 + l + 32];
    #pragma unroll
    for (int o = 16; o > 0; o >>= 1) c += __shfl_xor_sync(0xffffffffu, c, o);
    if (l == 0) g_c0 = c + batt[0];
}

// ---------------- CSR build: histogram ------------------------------------
__global__ void hist_kernel(const int* __restrict__ ei, int E) {
    int e = blockIdx.x * blockDim.x + threadIdx.x;
    if (e >= E) return;
    atomicAdd(g_cnt2 + __ldg(ei + E + e), 1);
}

// ---------------- CSR build: 3-phase exclusive scan ------------------------
__global__ void scanA_kernel() {
    __shared__ int s[256];
    int t = threadIdx.x;
    int i = blockIdx.x * 256 + t;
    int v = (i < NN) ? g_cnt2[i] : 0;
    s[t] = v;
    __syncthreads();
    #pragma unroll
    for (int off = 1; off < 256; off <<= 1) {
        int add = (t >= off) ? s[t - off] : 0;
        __syncthreads();
        s[t] += add;
        __syncthreads();
    }
    if (t == 255) g_bsum[blockIdx.x] = s[255];
}

__global__ void scanB_kernel() {
    __shared__ int s[512];
    int t = threadIdx.x;
    int v = (t < NBLK) ? g_bsum[t] : 0;
    s[t] = v;
    __syncthreads();
    #pragma unroll
    for (int off = 1; off < 512; off <<= 1) {
        int add = (t >= off) ? s[t - off] : 0;
        __syncthreads();
        s[t] += add;
        __syncthreads();
    }
    if (t < NBLK) g_boff[t] = s[t] - v;   // exclusive
}

__global__ void scanC_kernel() {
    __shared__ int s[256];
    int t = threadIdx.x;
    int i = blockIdx.x * 256 + t;
    int v = (i < NN) ? g_cnt2[i] : 0;
    s[t] = v;
    __syncthreads();
    #pragma unroll
    for (int off = 1; off < 256; off <<= 1) {
        int add = (t >= off) ? s[t - off] : 0;
        __syncthreads();
        s[t] += add;
        __syncthreads();
    }
    int base = g_boff[blockIdx.x];
    if (i < NN) {
        int excl = base + s[t] - v;
        g_off[i] = excl;
        g_pos[i] = excl;
        if (i == NN - 1) g_off[NN] = excl + v;   // == E
    }
}

// ---------------- CSR build: fill (eid,row) packed records -----------------
__global__ void fill_kernel(const int* __restrict__ ei, int E) {
    int e = blockIdx.x * blockDim.x + threadIdx.x;
    if (e >= E) return;
    int r = __ldg(ei + e);
    int c = __ldg(ei + E + e);
    int p = atomicAdd(g_pos + c, 1);
    g_epack[p] = ((unsigned long long)(unsigned)e << 32) | (unsigned)r;
}

// ---------------- K1: fused node GEMM: xl = x@W_l, xr(out) = x@W_r ---------
__global__ void node_gemm_kernel(const float* __restrict__ x,
                                 const float* __restrict__ Wl,
                                 const float* __restrict__ Wr,
                                 float* __restrict__ out, int N) {
    extern __shared__ float sm[];
    float* Wc = sm;                                   // 128x128 = 64KB
    const int tid  = threadIdx.x;
    const int lane = tid & 31;
    const int wid  = tid >> 5;
    float* xs = sm + 128 * 128 + wid * (8 * 128);     // 8 rows x 128 per warp

    for (int i = tid; i < 128 * 64; i += blockDim.x) {
        int k = i >> 6, j = i & 63;
        Wc[k * 128 + j]      = Wl[i];
        Wc[k * 128 + 64 + j] = Wr[i];
    }
    __syncthreads();

    int base = (blockIdx.x * 8 + wid) * 8;            // N % 8 == 0
    if (base >= N) return;

    const float4* xg = (const float4*)(x + (size_t)base * 128);
    #pragma unroll
    for (int i = 0; i < 8; i++)
        ((float4*)xs)[lane + 32 * i] = xg[lane + 32 * i];
    __syncwarp();

    unsigned long long acc[8][2];
    #pragma unroll
    for (int r = 0; r < 8; r++) { acc[r][0] = 0ull; acc[r][1] = 0ull; }

    #pragma unroll 4
    for (int k = 0; k < 128; k++) {
        ulonglong2 wv = *(const ulonglong2*)(Wc + k * 128 + lane * 4);
        #pragma unroll
        for (int r = 0; r < 8; r++) {
            unsigned long long xx = pk2(xs[r * 128 + k], xs[r * 128 + k]);
            ffma2(acc[r][0], xx, wv.x);
            ffma2(acc[r][1], xx, wv.y);
        }
    }

    #pragma unroll
    for (int r = 0; r < 8; r++) {
        int row = base + r;
        ulonglong2 v; v.x = acc[r][0]; v.y = acc[r][1];
        if (lane < 16)
            *(ulonglong2*)(g_xl + (size_t)row * 64 + lane * 4) = v;
        else
            *(ulonglong2*)(out + (size_t)row * 64 + (lane - 16) * 4) = v;
    }
}

// ---------------- K2: fused per-node pipeline ------------------------------
// Warp per node over a contiguous per-block chunk. Phase 1: gather-mean of
// xl rows (2x16 lanes, unroll 2) + finalize row + s_out. Phase 2: attention
// over ea rows (4x8 lanes, unroll 2), Z/asum in registers. Epilogue:
// row += Z@W_e + asum*b_e (W_e in smem), fused BN stats. No global scatter.
__global__ void __launch_bounds__(256)
fused_node_kernel(const float* __restrict__ ea,
                  const float* __restrict__ We,
                  const float* __restrict__ be,
                  const float* __restrict__ bl,
                  const float* __restrict__ watt,
                  float* __restrict__ out, int N) {
    __shared__ float sWe[2048];
    __shared__ float ss[64], sq[64];

    const int tid = threadIdx.x;
    const int wid = tid >> 5, lane = tid & 31;
    #pragma unroll
    for (int i = 0; i < 2; i++)
        ((float4*)sWe)[tid + 256 * i] = ((const float4*)We)[tid + 256 * i];
    if (tid < 64) { ss[tid] = 0.f; sq[tid] = 0.f; }
    __syncthreads();

    // hoisted per-lane constants
    const int grp16 = lane >> 4, l16 = lane & 15;
    const int grp8  = lane >> 3, l8  = lane & 7;
    const unsigned gmask = 0xFFu << (grp8 * 8);
    const float4 blv = ((const float4*)bl)[l16];
    const float4 wav = ((const float4*)watt)[l16];     // W_att[0:64]
    const float4 wc4 = ((const float4*)g_wc)[l8];
    const unsigned long long be2 = *(const unsigned long long*)(be + 2 * lane);
    const float c0 = g_c0;

    float aS0 = 0.f, aQ0 = 0.f, aS1 = 0.f, aQ1 = 0.f;  // BN partials

    int n0 = blockIdx.x * FCHUNK;
    int n1 = n0 + FCHUNK; if (n1 > N) n1 = N;

    for (int n = n0 + wid; n < n1; n += 8) {
        const int beg = __ldg(g_off + n), end = __ldg(g_off + n + 1);
        const int deg = end - beg;

        // ---- phase 1: xl gather-mean (2 groups of 16 lanes, unroll 2) ----
        float4 acc = make_float4(0.f, 0.f, 0.f, 0.f);
        {
            int i = beg + grp16;
            for (; i + 2 < end; i += 4) {
                unsigned r0 = (unsigned)(__ldg(g_epack + i)     & 0xffffffffull);
                unsigned r1 = (unsigned)(__ldg(g_epack + i + 2) & 0xffffffffull);
                float4 v0 = *(const float4*)(g_xl + (size_t)r0 * 64 + l16 * 4);
                float4 v1 = *(const float4*)(g_xl + (size_t)r1 * 64 + l16 * 4);
                acc.x += v0.x + v1.x; acc.y += v0.y + v1.y;
                acc.z += v0.z + v1.z; acc.w += v0.w + v1.w;
            }
            if (i < end) {
                unsigned r0 = (unsigned)(__ldg(g_epack + i) & 0xffffffffull);
                float4 v0 = *(const float4*)(g_xl + (size_t)r0 * 64 + l16 * 4);
                acc.x += v0.x; acc.y += v0.y; acc.z += v0.z; acc.w += v0.w;
            }
        }
        acc.x += __shfl_xor_sync(0xffffffffu, acc.x, 16);
        acc.y += __shfl_xor_sync(0xffffffffu, acc.y, 16);
        acc.z += __shfl_xor_sync(0xffffffffu, acc.z, 16);
        acc.w += __shfl_xor_sync(0xffffffffu, acc.w, 16);

        // finalize row (group 0 lanes hold it as float4) + s_out
        float4 o = make_float4(0.f, 0.f, 0.f, 0.f);
        float p = 0.f;
        if (grp16 == 0) {
            float inv = 1.0f / fmaxf((float)deg, 1.0f);
            o = *(const float4*)(out + (size_t)n * 64 + l16 * 4);  // x@W_r
            o.x = fmaf(acc.x, inv, o.x) + blv.x;
            o.y = fmaf(acc.y, inv, o.y) + blv.y;
            o.z = fmaf(acc.z, inv, o.z) + blv.z;
            o.w = fmaf(acc.w, inv, o.w) + blv.w;
            p = o.x * wav.x + o.y * wav.y + o.z * wav.z + o.w * wav.w;
            p += __shfl_xor_sync(0x0000ffffu, p, 1);
            p += __shfl_xor_sync(0x0000ffffu, p, 2);
            p += __shfl_xor_sync(0x0000ffffu, p, 4);
            p += __shfl_xor_sync(0x0000ffffu, p, 8);
        }
        const float zbias = __shfl_sync(0xffffffffu, p, 0) + c0;

        // ---- phase 2: attention over ea (4 groups of 8 lanes, unroll 2) --
        float4 accZ = make_float4(0.f, 0.f, 0.f, 0.f);
        float asum = 0.f;
        {
            int i = beg + grp8;
            for (; i + 4 < end; i += 8) {
                unsigned e0 = (unsigned)(__ldg(g_epack + i)     >> 32);
                unsigned e1 = (unsigned)(__ldg(g_epack + i + 4) >> 32);
                float4 a0 = __ldg((const float4*)ea + (size_t)e0 * 8 + l8);
                float4 a1 = __ldg((const float4*)ea + (size_t)e1 * 8 + l8);
                float p0 = a0.x*wc4.x + a0.y*wc4.y + a0.z*wc4.z + a0.w*wc4.w;
                float p1 = a1.x*wc4.x + a1.y*wc4.y + a1.z*wc4.z + a1.w*wc4.w;
                p0 += __shfl_xor_sync(gmask, p0, 1);
                p1 += __shfl_xor_sync(gmask, p1, 1);
                p0 += __shfl_xor_sync(gmask, p0, 2);
                p1 += __shfl_xor_sync(gmask, p1, 2);
                p0 += __shfl_xor_sync(gmask, p0, 4);
                p1 += __shfl_xor_sync(gmask, p1, 4);
                float t0 = 1.0f / (1.0f + __expf(-(p0 + zbias)));
                float t1 = 1.0f / (1.0f + __expf(-(p1 + zbias)));
                accZ.x = fmaf(t0, a0.x, fmaf(t1, a1.x, accZ.x));
                accZ.y = fmaf(t0, a0.y, fmaf(t1, a1.y, accZ.y));
                accZ.z = fmaf(t0, a0.z, fmaf(t1, a1.z, accZ.z));
                accZ.w = fmaf(t0, a0.w, fmaf(t1, a1.w, accZ.w));
                if (l8 == 0) asum += t0 + t1;
            }
            if (i < end) {
                unsigned e0 = (unsigned)(__ldg(g_epack + i) >> 32);
                float4 a0 = __ldg((const float4*)ea + (size_t)e0 * 8 + l8);
                float p0 = a0.x*wc4.x + a0.y*wc4.y + a0.z*wc4.z + a0.w*wc4.w;
                p0 += __shfl_xor_sync(gmask, p0, 1);
                p0 += __shfl_xor_sync(gmask, p0, 2);
                p0 += __shfl_xor_sync(gmask, p0, 4);
                float t0 = 1.0f / (1.0f + __expf(-(p0 + zbias)));
                accZ.x = fmaf(t0, a0.x, accZ.x);
                accZ.y = fmaf(t0, a0.y, accZ.y);
                accZ.z = fmaf(t0, a0.z, accZ.z);
                accZ.w = fmaf(t0, a0.w, accZ.w);
                if (l8 == 0) asum += t0;
            }
        }
        // combine groups (all lanes reconverged)
        accZ.x += __shfl_xor_sync(0xffffffffu, accZ.x, 8);
        accZ.y += __shfl_xor_sync(0xffffffffu, accZ.y, 8);
        accZ.z += __shfl_xor_sync(0xffffffffu, accZ.z, 8);
        accZ.w += __shfl_xor_sync(0xffffffffu, accZ.w, 8);
        accZ.x += __shfl_xor_sync(0xffffffffu, accZ.x, 16);
        accZ.y += __shfl_xor_sync(0xffffffffu, accZ.y, 16);
        accZ.z += __shfl_xor_sync(0xffffffffu, accZ.z, 16);
        accZ.w += __shfl_xor_sync(0xffffffffu, accZ.w, 16);
        #pragma unroll
        for (int s = 1; s <= 16; s <<= 1)
            asum += __shfl_xor_sync(0xffffffffu, asum, s);

        // ---- epilogue: lane owns channels 2*lane, 2*lane+1 ----------------
        // Source lane (lane>>1) holds channels [4*(lane>>1), 4*(lane>>1)+4)
        // in o.x..o.w. Shuffle ALL components from the source, then select
        // locally by destination parity (selector on dest, not source!).
        float ox = __shfl_sync(0xffffffffu, o.x, lane >> 1);
        float oy = __shfl_sync(0xffffffffu, o.y, lane >> 1);
        float oz = __shfl_sync(0xffffffffu, o.z, lane >> 1);
        float ow = __shfl_sync(0xffffffffu, o.w, lane >> 1);
        float r0 = (lane & 1) ? oz : ox;
        float r1 = (lane & 1) ? ow : oy;
        unsigned long long a64 = pk2(r0, r1);
        ffma2(a64, pk2(asum, asum), be2);
        #pragma unroll
        for (int k = 0; k < 32; k++) {
            float comp = ((k & 3) == 0) ? accZ.x : ((k & 3) == 1) ? accZ.y
                       : ((k & 3) == 2) ? accZ.z : accZ.w;
            float zk = __shfl_sync(0xffffffffu, comp, k >> 2);
            unsigned long long w2 =
                *(const unsigned long long*)(sWe + k * 64 + 2 * lane);
            ffma2(a64, pk2(zk, zk), w2);
        }
        *(unsigned long long*)(out + (size_t)n * 64 + 2 * lane) = a64;
        float v0 = lo32(a64), v1 = hi32(a64);
        aS0 += v0; aQ0 = fmaf(v0, v0, aQ0);
        aS1 += v1; aQ1 = fmaf(v1, v1, aQ1);
    }

    // block-level BN reduction, then ONE global atomic per channel per block
    __syncthreads();
    atomicAdd(&ss[2 * lane],     aS0);
    atomicAdd(&ss[2 * lane + 1], aS1);
    atomicAdd(&sq[2 * lane],     aQ0);
    atomicAdd(&sq[2 * lane + 1], aQ1);
    __syncthreads();
    if (tid < 64) {
        atomicAdd(g_sums + tid,      ss[tid]);
        atomicAdd(g_sums + 64 + tid, sq[tid]);
    }
}

// ---------------- K5b: fold BN + residual-double into scale/shift ----------
__global__ void bn_coef_kernel(const float* __restrict__ gamma,
                               const float* __restrict__ beta, float invN) {
    int c = threadIdx.x;
    float mu  = g_sums[c] * invN;
    float var = g_sums[64 + c] * invN - mu * mu;
    float r = rsqrtf(var + 1e-5f);
    float g = gamma[c];
    g_coef[c] = make_float2(2.0f * g * r, 2.0f * (beta[c] - g * mu * r));
}

// ---------------- K6: apply (float4) ---------------------------------------
__global__ void bn_apply_kernel(float* __restrict__ out, int total4) {
    int i = blockIdx.x * blockDim.x + threadIdx.x;
    if (i >= total4) return;
    int c = (i * 4) & 63;
    float2 c0 = g_coef[c], c1 = g_coef[c + 1], c2 = g_coef[c + 2], c3 = g_coef[c + 3];
    float4 v = ((const float4*)out)[i];
    v.x = fmaxf(fmaf(v.x, c0.x, c0.y), 0.0f);
    v.y = fmaxf(fmaf(v.y, c1.x, c1.y), 0.0f);
    v.z = fmaxf(fmaf(v.z, c2.x, c2.y), 0.0f);
    v.w = fmaxf(fmaf(v.w, c3.x, c3.y), 0.0f);
    ((float4*)out)[i] = v;
}

// ---------------- launch ----------------------------------------------------
extern "C" void kernel_launch(void* const* d_in, const int* in_sizes, int n_in,
                              void* d_out, int out_size) {
    const float* x     = (const float*)d_in[0];
    const int*   ei    = (const int*)  d_in[1];
    const float* ea    = (const float*)d_in[2];
    const float* Wl    = (const float*)d_in[3];
    const float* bl    = (const float*)d_in[4];
    const float* Wr    = (const float*)d_in[5];
    const float* We    = (const float*)d_in[6];
    const float* be    = (const float*)d_in[7];
    const float* watt  = (const float*)d_in[8];
    const float* batt  = (const float*)d_in[9];
    const float* gamma = (const float*)d_in[10];
    const float* beta  = (const float*)d_in[11];
    float* out = (float*)d_out;

    int N = in_sizes[0] / 128;   // 100000
    int E = in_sizes[1] / 2;     // 1000000

    cudaFuncSetAttribute(node_gemm_kernel,
                         cudaFuncAttributeMaxDynamicSharedMemorySize, 98304);

    zero_kernel<<<NBLK, 256>>>();
    prep_kernel<<<1, 32>>>(We, be, watt, batt);
    hist_kernel<<<(E + 255) / 256, 256>>>(ei, E);
    scanA_kernel<<<NBLK, 256>>>();
    scanB_kernel<<<1, 512>>>();
    scanC_kernel<<<NBLK, 256>>>();
    fill_kernel<<<(E + 255) / 256, 256>>>(ei, E);
    node_gemm_kernel<<<(N + 63) / 64, 256, 98304>>>(x, Wl, Wr, out, N);
    fused_node_kernel<<<FGRID, 256>>>(ea, We, be, bl, watt, out, N);
    bn_coef_kernel<<<1, 64>>>(gamma, beta, 1.0f / (float)N);
    bn_apply_kernel<<<(N * 16 + 255) / 256, 256>>>(out, N * 16);
}

// round 9
// speedup vs baseline: 1.1700x; 1.0154x over previous
#include <cuda_runtime.h>
#include <math.h>

// Problem constants (shapes fixed for this problem instance)
#define NN 100000
#define NE 1000000
#define NBLK 391          // ceil(NN/256)
#define FGRID 1184        // fused kernel grid (8*148)
#define FCHUNK 85         // ceil(NN/FGRID)

// ---------------- scratch (static device globals; no allocation) ----------
__device__ float g_xl  [NN * 64];           // x @ W_l
__device__ float g_wc  [32];                // W_e @ W_att[64:128]
__device__ float g_c0;                      // b_e . W_att[64:128] + b_att
__device__ float g_sums[128];               // [0:64) sum, [64:128) sumsq
// CSR build
__device__ int   g_cnt2[NN];                // in-degree histogram
__device__ int   g_off [NN + 1];            // exclusive offsets
__device__ int   g_pos [NN];                // running fill cursor
__device__ int   g_bsum[512];               // per-block partial sums
__device__ int   g_boff[512];               // scanned partials
__device__ unsigned long long g_epack[NE];  // (eid<<32)|row, grouped by col

// ---------------- packed f32x2 helpers -------------------------------------
__device__ __forceinline__ unsigned long long pk2(float a, float b) {
    unsigned long long r;
    asm("mov.b64 %0, {%1, %2};" : "=l"(r) : "f"(a), "f"(b));
    return r;
}
__device__ __forceinline__ void ffma2(unsigned long long& d,
                                      unsigned long long a,
                                      unsigned long long b) {
    asm("fma.rn.f32x2 %0, %1, %2, %0;" : "+l"(d) : "l"(a), "l"(b));
}
__device__ __forceinline__ float lo32(unsigned long long v) {
    return __uint_as_float((unsigned)(v & 0xffffffffu));
}
__device__ __forceinline__ float hi32(unsigned long long v) {
    return __uint_as_float((unsigned)(v >> 32));
}

// ---------------- K0: zero scratch + prep constants (merged) ---------------
// Blocks [0, NBLK) zero g_cnt2/g_sums; block NBLK (one warp) computes
// wc = W_e @ W_att[64:128] and c0 = b_e . W_att[64:128] + b_att.
__global__ void zero_prep_kernel(const float* __restrict__ We,
                                 const float* __restrict__ be,
                                 const float* __restrict__ watt,
                                 const float* __restrict__ batt) {
    if (blockIdx.x == NBLK) {
        int l = threadIdx.x;
        if (l < 32) {
            float s = 0.f;
            #pragma unroll
            for (int j = 0; j < 64; j++)
                s = fmaf(We[l * 64 + j], watt[64 + j], s);
            g_wc[l] = s;
            float c = be[l] * watt[64 + l] + be[l + 32] * watt[64 + l + 32];
            #pragma unroll
            for (int o = 16; o > 0; o >>= 1)
                c += __shfl_xor_sync(0xffffffffu, c, o);
            if (l == 0) g_c0 = c + batt[0];
        }
        return;
    }
    int i = blockIdx.x * blockDim.x + threadIdx.x;
    if (i < NN)  g_cnt2[i] = 0;
    if (i < 128) g_sums[i] = 0.0f;
}

// ---------------- CSR build: histogram ------------------------------------
__global__ void hist_kernel(const int* __restrict__ ei, int E) {
    int e = blockIdx.x * blockDim.x + threadIdx.x;
    if (e >= E) return;
    atomicAdd(g_cnt2 + __ldg(ei + E + e), 1);
}

// ---------------- CSR build: 3-phase exclusive scan ------------------------
__global__ void scanA_kernel() {
    __shared__ int s[256];
    int t = threadIdx.x;
    int i = blockIdx.x * 256 + t;
    int v = (i < NN) ? g_cnt2[i] : 0;
    s[t] = v;
    __syncthreads();
    #pragma unroll
    for (int off = 1; off < 256; off <<= 1) {
        int add = (t >= off) ? s[t - off] : 0;
        __syncthreads();
        s[t] += add;
        __syncthreads();
    }
    if (t == 255) g_bsum[blockIdx.x] = s[255];
}

__global__ void scanB_kernel() {
    __shared__ int s[512];
    int t = threadIdx.x;
    int v = (t < NBLK) ? g_bsum[t] : 0;
    s[t] = v;
    __syncthreads();
    #pragma unroll
    for (int off = 1; off < 512; off <<= 1) {
        int add = (t >= off) ? s[t - off] : 0;
        __syncthreads();
        s[t] += add;
        __syncthreads();
    }
    if (t < NBLK) g_boff[t] = s[t] - v;   // exclusive
}

__global__ void scanC_kernel() {
    __shared__ int s[256];
    int t = threadIdx.x;
    int i = blockIdx.x * 256 + t;
    int v = (i < NN) ? g_cnt2[i] : 0;
    s[t] = v;
    __syncthreads();
    #pragma unroll
    for (int off = 1; off < 256; off <<= 1) {
        int add = (t >= off) ? s[t - off] : 0;
        __syncthreads();
        s[t] += add;
        __syncthreads();
    }
    int base = g_boff[blockIdx.x];
    if (i < NN) {
        int excl = base + s[t] - v;
        g_off[i] = excl;
        g_pos[i] = excl;
        if (i == NN - 1) g_off[NN] = excl + v;   // == E
    }
}

// ---------------- CSR build: fill (eid,row) packed records -----------------
__global__ void fill_kernel(const int* __restrict__ ei, int E) {
    int e = blockIdx.x * blockDim.x + threadIdx.x;
    if (e >= E) return;
    int r = __ldg(ei + e);
    int c = __ldg(ei + E + e);
    int p = atomicAdd(g_pos + c, 1);
    g_epack[p] = ((unsigned long long)(unsigned)e << 32) | (unsigned)r;
}

// ---------------- K1: fused node GEMM: xl = x@W_l, xr(out) = x@W_r ---------
// Launched 4th so ncu's fixed capture window profiles it.
__global__ void node_gemm_kernel(const float* __restrict__ x,
                                 const float* __restrict__ Wl,
                                 const float* __restrict__ Wr,
                                 float* __restrict__ out, int N) {
    extern __shared__ float sm[];
    float* Wc = sm;                                   // 128x128 = 64KB
    const int tid  = threadIdx.x;
    const int lane = tid & 31;
    const int wid  = tid >> 5;
    float* xs = sm + 128 * 128 + wid * (8 * 128);     // 8 rows x 128 per warp

    for (int i = tid; i < 128 * 64; i += blockDim.x) {
        int k = i >> 6, j = i & 63;
        Wc[k * 128 + j]      = Wl[i];
        Wc[k * 128 + 64 + j] = Wr[i];
    }
    __syncthreads();

    int base = (blockIdx.x * 8 + wid) * 8;            // N % 8 == 0
    if (base >= N) return;

    const float4* xg = (const float4*)(x + (size_t)base * 128);
    #pragma unroll
    for (int i = 0; i < 8; i++)
        ((float4*)xs)[lane + 32 * i] = xg[lane + 32 * i];
    __syncwarp();

    unsigned long long acc[8][2];
    #pragma unroll
    for (int r = 0; r < 8; r++) { acc[r][0] = 0ull; acc[r][1] = 0ull; }

    #pragma unroll 4
    for (int k = 0; k < 128; k++) {
        ulonglong2 wv = *(const ulonglong2*)(Wc + k * 128 + lane * 4);
        #pragma unroll
        for (int r = 0; r < 8; r++) {
            unsigned long long xx = pk2(xs[r * 128 + k], xs[r * 128 + k]);
            ffma2(acc[r][0], xx, wv.x);
            ffma2(acc[r][1], xx, wv.y);
        }
    }

    #pragma unroll
    for (int r = 0; r < 8; r++) {
        int row = base + r;
        ulonglong2 v; v.x = acc[r][0]; v.y = acc[r][1];
        if (lane < 16)
            *(ulonglong2*)(g_xl + (size_t)row * 64 + lane * 4) = v;
        else
            *(ulonglong2*)(out + (size_t)row * 64 + (lane - 16) * 4) = v;
    }
}

// ---------------- K2: fused per-node pipeline ------------------------------
__global__ void __launch_bounds__(256)
fused_node_kernel(const float* __restrict__ ea,
                  const float* __restrict__ We,
                  const float* __restrict__ be,
                  const float* __restrict__ bl,
                  const float* __restrict__ watt,
                  float* __restrict__ out, int N) {
    __shared__ float sWe[2048];
    __shared__ float ss[64], sq[64];

    const int tid = threadIdx.x;
    const int wid = tid >> 5, lane = tid & 31;
    #pragma unroll
    for (int i = 0; i < 2; i++)
        ((float4*)sWe)[tid + 256 * i] = ((const float4*)We)[tid + 256 * i];
    if (tid < 64) { ss[tid] = 0.f; sq[tid] = 0.f; }
    __syncthreads();

    // hoisted per-lane constants
    const int grp16 = lane >> 4, l16 = lane & 15;
    const int grp8  = lane >> 3, l8  = lane & 7;
    const unsigned gmask = 0xFFu << (grp8 * 8);
    const float4 blv = ((const float4*)bl)[l16];
    const float4 wav = ((const float4*)watt)[l16];     // W_att[0:64]
    const float4 wc4 = ((const float4*)g_wc)[l8];
    const unsigned long long be2 = *(const unsigned long long*)(be + 2 * lane);
    const float c0 = g_c0;

    float aS0 = 0.f, aQ0 = 0.f, aS1 = 0.f, aQ1 = 0.f;  // BN partials

    int n0 = blockIdx.x * FCHUNK;
    int n1 = n0 + FCHUNK; if (n1 > N) n1 = N;

    for (int n = n0 + wid; n < n1; n += 8) {
        const int beg = __ldg(g_off + n), end = __ldg(g_off + n + 1);
        const int deg = end - beg;

        // ---- phase 1: xl gather-mean (2 groups of 16 lanes, unroll 2) ----
        float4 acc = make_float4(0.f, 0.f, 0.f, 0.f);
        {
            int i = beg + grp16;
            for (; i + 2 < end; i += 4) {
                unsigned r0 = (unsigned)(__ldg(g_epack + i)     & 0xffffffffull);
                unsigned r1 = (unsigned)(__ldg(g_epack + i + 2) & 0xffffffffull);
                float4 v0 = *(const float4*)(g_xl + (size_t)r0 * 64 + l16 * 4);
                float4 v1 = *(const float4*)(g_xl + (size_t)r1 * 64 + l16 * 4);
                acc.x += v0.x + v1.x; acc.y += v0.y + v1.y;
                acc.z += v0.z + v1.z; acc.w += v0.w + v1.w;
            }
            if (i < end) {
                unsigned r0 = (unsigned)(__ldg(g_epack + i) & 0xffffffffull);
                float4 v0 = *(const float4*)(g_xl + (size_t)r0 * 64 + l16 * 4);
                acc.x += v0.x; acc.y += v0.y; acc.z += v0.z; acc.w += v0.w;
            }
        }
        acc.x += __shfl_xor_sync(0xffffffffu, acc.x, 16);
        acc.y += __shfl_xor_sync(0xffffffffu, acc.y, 16);
        acc.z += __shfl_xor_sync(0xffffffffu, acc.z, 16);
        acc.w += __shfl_xor_sync(0xffffffffu, acc.w, 16);

        // finalize row (group 0 lanes hold it as float4) + s_out
        float4 o = make_float4(0.f, 0.f, 0.f, 0.f);
        float p = 0.f;
        if (grp16 == 0) {
            float inv = 1.0f / fmaxf((float)deg, 1.0f);
            o = *(const float4*)(out + (size_t)n * 64 + l16 * 4);  // x@W_r
            o.x = fmaf(acc.x, inv, o.x) + blv.x;
            o.y = fmaf(acc.y, inv, o.y) + blv.y;
            o.z = fmaf(acc.z, inv, o.z) + blv.z;
            o.w = fmaf(acc.w, inv, o.w) + blv.w;
            p = o.x * wav.x + o.y * wav.y + o.z * wav.z + o.w * wav.w;
            p += __shfl_xor_sync(0x0000ffffu, p, 1);
            p += __shfl_xor_sync(0x0000ffffu, p, 2);
            p += __shfl_xor_sync(0x0000ffffu, p, 4);
            p += __shfl_xor_sync(0x0000ffffu, p, 8);
        }
        const float zbias = __shfl_sync(0xffffffffu, p, 0) + c0;

        // ---- phase 2: attention over ea (4 groups of 8 lanes, unroll 2) --
        float4 accZ = make_float4(0.f, 0.f, 0.f, 0.f);
        float asum = 0.f;
        {
            int i = beg + grp8;
            for (; i + 4 < end; i += 8) {
                unsigned e0 = (unsigned)(__ldg(g_epack + i)     >> 32);
                unsigned e1 = (unsigned)(__ldg(g_epack + i + 4) >> 32);
                float4 a0 = __ldg((const float4*)ea + (size_t)e0 * 8 + l8);
                float4 a1 = __ldg((const float4*)ea + (size_t)e1 * 8 + l8);
                float p0 = a0.x*wc4.x + a0.y*wc4.y + a0.z*wc4.z + a0.w*wc4.w;
                float p1 = a1.x*wc4.x + a1.y*wc4.y + a1.z*wc4.z + a1.w*wc4.w;
                p0 += __shfl_xor_sync(gmask, p0, 1);
                p1 += __shfl_xor_sync(gmask, p1, 1);
                p0 += __shfl_xor_sync(gmask, p0, 2);
                p1 += __shfl_xor_sync(gmask, p1, 2);
                p0 += __shfl_xor_sync(gmask, p0, 4);
                p1 += __shfl_xor_sync(gmask, p1, 4);
                float t0 = 1.0f / (1.0f + __expf(-(p0 + zbias)));
                float t1 = 1.0f / (1.0f + __expf(-(p1 + zbias)));
                accZ.x = fmaf(t0, a0.x, fmaf(t1, a1.x, accZ.x));
                accZ.y = fmaf(t0, a0.y, fmaf(t1, a1.y, accZ.y));
                accZ.z = fmaf(t0, a0.z, fmaf(t1, a1.z, accZ.z));
                accZ.w = fmaf(t0, a0.w, fmaf(t1, a1.w, accZ.w));
                if (l8 == 0) asum += t0 + t1;
            }
            if (i < end) {
                unsigned e0 = (unsigned)(__ldg(g_epack + i) >> 32);
                float4 a0 = __ldg((const float4*)ea + (size_t)e0 * 8 + l8);
                float p0 = a0.x*wc4.x + a0.y*wc4.y + a0.z*wc4.z + a0.w*wc4.w;
                p0 += __shfl_xor_sync(gmask, p0, 1);
                p0 += __shfl_xor_sync(gmask, p0, 2);
                p0 += __shfl_xor_sync(gmask, p0, 4);
                float t0 = 1.0f / (1.0f + __expf(-(p0 + zbias)));
                accZ.x = fmaf(t0, a0.x, accZ.x);
                accZ.y = fmaf(t0, a0.y, accZ.y);
                accZ.z = fmaf(t0, a0.z, accZ.z);
                accZ.w = fmaf(t0, a0.w, accZ.w);
                if (l8 == 0) asum += t0;
            }
        }
        // combine groups (all lanes reconverged)
        accZ.x += __shfl_xor_sync(0xffffffffu, accZ.x, 8);
        accZ.y += __shfl_xor_sync(0xffffffffu, accZ.y, 8);
        accZ.z += __shfl_xor_sync(0xffffffffu, accZ.z, 8);
        accZ.w += __shfl_xor_sync(0xffffffffu, accZ.w, 8);
        accZ.x += __shfl_xor_sync(0xffffffffu, accZ.x, 16);
        accZ.y += __shfl_xor_sync(0xffffffffu, accZ.y, 16);
        accZ.z += __shfl_xor_sync(0xffffffffu, accZ.z, 16);
        accZ.w += __shfl_xor_sync(0xffffffffu, accZ.w, 16);
        #pragma unroll
        for (int s = 1; s <= 16; s <<= 1)
            asum += __shfl_xor_sync(0xffffffffu, asum, s);

        // ---- epilogue: lane owns channels 2*lane, 2*lane+1 ----------------
        // Shuffle all 4 components from source lane (lane>>1), select by
        // DESTINATION parity.
        float ox = __shfl_sync(0xffffffffu, o.x, lane >> 1);
        float oy = __shfl_sync(0xffffffffu, o.y, lane >> 1);
        float oz = __shfl_sync(0xffffffffu, o.z, lane >> 1);
        float ow = __shfl_sync(0xffffffffu, o.w, lane >> 1);
        float r0 = (lane & 1) ? oz : ox;
        float r1 = (lane & 1) ? ow : oy;
        unsigned long long a64 = pk2(r0, r1);
        ffma2(a64, pk2(asum, asum), be2);
        #pragma unroll
        for (int k = 0; k < 32; k++) {
            float comp = ((k & 3) == 0) ? accZ.x : ((k & 3) == 1) ? accZ.y
                       : ((k & 3) == 2) ? accZ.z : accZ.w;
            float zk = __shfl_sync(0xffffffffu, comp, k >> 2);
            unsigned long long w2 =
                *(const unsigned long long*)(sWe + k * 64 + 2 * lane);
            ffma2(a64, pk2(zk, zk), w2);
        }
        *(unsigned long long*)(out + (size_t)n * 64 + 2 * lane) = a64;
        float v0 = lo32(a64), v1 = hi32(a64);
        aS0 += v0; aQ0 = fmaf(v0, v0, aQ0);
        aS1 += v1; aQ1 = fmaf(v1, v1, aQ1);
    }

    // block-level BN reduction, then ONE global atomic per channel per block
    __syncthreads();
    atomicAdd(&ss[2 * lane],     aS0);
    atomicAdd(&ss[2 * lane + 1], aS1);
    atomicAdd(&sq[2 * lane],     aQ0);
    atomicAdd(&sq[2 * lane + 1], aQ1);
    __syncthreads();
    if (tid < 64) {
        atomicAdd(g_sums + tid,      ss[tid]);
        atomicAdd(g_sums + 64 + tid, sq[tid]);
    }
}

// ---------------- K6: BN coef (recomputed per block) + apply ----------------
// relu(2*(gamma*(v-mu)*rsqrt(var+eps)+beta)) = relu(v*sc + sf)
__global__ void bn_apply_kernel(const float* __restrict__ gamma,
                                const float* __restrict__ beta,
                                float* __restrict__ out, int total4,
                                float invN) {
    __shared__ float2 scoef[64];
    int t = threadIdx.x;
    if (t < 64) {
        float mu  = g_sums[t] * invN;
        float var = g_sums[64 + t] * invN - mu * mu;
        float r = rsqrtf(var + 1e-5f);
        float g = gamma[t];
        scoef[t] = make_float2(2.0f * g * r, 2.0f * (beta[t] - g * mu * r));
    }
    __syncthreads();
    int i = blockIdx.x * blockDim.x + t;
    if (i >= total4) return;
    int c = (i * 4) & 63;
    float2 c0 = scoef[c], c1 = scoef[c + 1], c2 = scoef[c + 2], c3 = scoef[c + 3];
    float4 v = ((const float4*)out)[i];
    v.x = fmaxf(fmaf(v.x, c0.x, c0.y), 0.0f);
    v.y = fmaxf(fmaf(v.y, c1.x, c1.y), 0.0f);
    v.z = fmaxf(fmaf(v.z, c2.x, c2.y), 0.0f);
    v.w = fmaxf(fmaf(v.w, c3.x, c3.y), 0.0f);
    ((float4*)out)[i] = v;
}

// ---------------- launch ----------------------------------------------------
extern "C" void kernel_launch(void* const* d_in, const int* in_sizes, int n_in,
                              void* d_out, int out_size) {
    const float* x     = (const float*)d_in[0];
    const int*   ei    = (const int*)  d_in[1];
    const float* ea    = (const float*)d_in[2];
    const float* Wl    = (const float*)d_in[3];
    const float* bl    = (const float*)d_in[4];
    const float* Wr    = (const float*)d_in[5];
    const float* We    = (const float*)d_in[6];
    const float* be    = (const float*)d_in[7];
    const float* watt  = (const float*)d_in[8];
    const float* batt  = (const float*)d_in[9];
    const float* gamma = (const float*)d_in[10];
    const float* beta  = (const float*)d_in[11];
    float* out = (float*)d_out;

    int N = in_sizes[0] / 128;   // 100000
    int E = in_sizes[1] / 2;     // 1000000

    cudaFuncSetAttribute(node_gemm_kernel,
                         cudaFuncAttributeMaxDynamicSharedMemorySize, 98304);

    // Launch order matters: ncu captures the 4th launch -> node_gemm.
    zero_prep_kernel<<<NBLK + 1, 256>>>(We, be, watt, batt);          // 1
    hist_kernel<<<(E + 255) / 256, 256>>>(ei, E);                     // 2
    scanA_kernel<<<NBLK, 256>>>();                                    // 3
    node_gemm_kernel<<<(N + 63) / 64, 256, 98304>>>(x, Wl, Wr, out, N); // 4 (profiled)
    scanB_kernel<<<1, 512>>>();                                       // 5
    scanC_kernel<<<NBLK, 256>>>();                                    // 6
    fill_kernel<<<(E + 255) / 256, 256>>>(ei, E);                     // 7
    fused_node_kernel<<<FGRID, 256>>>(ea, We, be, bl, watt, out, N);  // 8
    bn_apply_kernel<<<(N * 16 + 255) / 256, 256>>>(gamma, beta, out,
                                                   N * 16, 1.0f / (float)N); // 9
}